// round 13
// baseline (speedup 1.0000x reference)
#include <cuda_runtime.h>
#include <cstdint>

#define GH 96
#define GW 96
#define HW (GH*GW)
#define BSZ 8
#define LN 16
#define PN 16
#define NCELL (BSZ*GH*GW)   /* 73728 */
#define TPB 128
#define NBLK (NCELL/TPB)    /* 576 */
#define STG 6               /* cp.async pipeline depth (predictors ahead) */

__device__ float g_partials[NBLK];
__device__ unsigned int g_ticket;   // zero-init; last block resets it

typedef unsigned long long u64;

__device__ __forceinline__ float asqrt(float x) {
    float r;
    asm("sqrt.approx.f32 %0, %1;" : "=f"(r) : "f"(x));
    return r;
}
__device__ __forceinline__ float arcp(float x) {
    float r;
    asm("rcp.approx.f32 %0, %1;" : "=f"(r) : "f"(x));
    return r;
}
__device__ __forceinline__ u64 pk2(float a, float b) {
    u64 r; asm("mov.b64 %0, {%1, %2};" : "=l"(r) : "f"(a), "f"(b)); return r;
}
__device__ __forceinline__ void upk2(float& a, float& b, u64 v) {
    asm("mov.b64 {%0, %1}, %2;" : "=f"(a), "=f"(b) : "l"(v));
}
__device__ __forceinline__ u64 add2(u64 a, u64 b) {
    u64 r; asm("add.rn.f32x2 %0, %1, %2;" : "=l"(r) : "l"(a), "l"(b)); return r;
}
__device__ __forceinline__ u64 mul2(u64 a, u64 b) {
    u64 r; asm("mul.rn.f32x2 %0, %1, %2;" : "=l"(r) : "l"(a), "l"(b)); return r;
}
__device__ __forceinline__ u64 fma2(u64 a, u64 b, u64 c) {
    u64 r; asm("fma.rn.f32x2 %0, %1, %2, %3;" : "=l"(r) : "l"(a), "l"(b), "l"(c)); return r;
}
__device__ __forceinline__ void cp_async4(uint32_t smem_dst, const float* gsrc) {
    asm volatile("cp.async.ca.shared.global [%0], [%1], 4;"
                 :: "r"(smem_dst), "l"(gsrc));
}
__device__ __forceinline__ void cp_commit() {
    asm volatile("cp.async.commit_group;");
}
template <int N>
__device__ __forceinline__ void cp_wait() {
    asm volatile("cp.async.wait_group %0;" :: "n"(N));
}

__global__ __launch_bounds__(TPB, 4)
void yolino_main(const float* __restrict__ target, const float* __restrict__ pred,
                 float* __restrict__ out)
{
    const int tid = threadIdx.x;
    const int n   = blockIdx.x * TPB + tid;         // n in [0, NCELL)
    const int w   = n % GW;
    const int t1  = n / GW;
    const int h   = t1 % GH;
    const int b   = t1 / GH;

    const float* tb = target + b * (64 * HW) + h * GW + w;
    const float* pb = pred   + b * (96 * HW) + h * GW + w;

    // Staged pred channels: sp[stage][channel][thread].
    __shared__ float sp[STG][6][TPB];

    // Prologue: issue STG stages of async copies (6 x 4B per thread per stage).
    #pragma unroll
    for (int s = 0; s < STG; ++s) {
        const float* src = pb + s * (6 * HW);
        #pragma unroll
        for (int ch = 0; ch < 6; ++ch) {
            uint32_t dst = (uint32_t)__cvta_generic_to_shared(&sp[s][ch][tid]);
            cp_async4(dst, src + ch * HW);
        }
        cp_commit();
    }

    // Target lines (one-time front batch), packed endpoint pairs.
    u64 tx[LN], ty[LN];
    unsigned tmask = 0;
    #pragma unroll
    for (int l = 0; l < LN; ++l) {
        float x1 = tb[(l * 4 + 0) * HW];
        float y1 = tb[(l * 4 + 1) * HW];
        float x2 = tb[(l * 4 + 2) * HW];
        float y2 = tb[(l * 4 + 3) * HW];
        tx[l] = pk2(x1, x2);
        ty[l] = pk2(y1, y2);
        float s = (x1 + y1) + (x2 + y2);
        if (s > 0.f) tmask |= (1u << l);
    }

    float loss = 0.f;
    int slot = 0;

    #pragma unroll 1
    for (int p = 0; p < PN; ++p) {
        // Wait for stage p. While still issuing (p < PN-STG) keep STG-1 pending;
        // at p == PN-STG everything is issued -> drain all (one-time cost).
        if (p < PN - STG)       cp_wait<STG - 1>();
        else if (p == PN - STG) cp_wait<0>();

        // Consume own slot (each thread reads what it wrote: no barrier needed).
        const float c0 = sp[slot][0][tid];
        const float c1 = sp[slot][1][tid];
        const float c2 = sp[slot][2][tid];
        const float c3 = sp[slot][3][tid];
        const float c4 = sp[slot][4][tid];
        const float c5 = sp[slot][5][tid];

        // Refill this slot with stage p+STG.
        if (p + STG < PN) {
            const float* src = pb + (p + STG) * (6 * HW);
            #pragma unroll
            for (int ch = 0; ch < 6; ++ch) {
                uint32_t dst = (uint32_t)__cvta_generic_to_shared(&sp[slot][ch][tid]);
                cp_async4(dst, src + ch * HW);
            }
            cp_commit();
        }
        if (++slot == STG) slot = 0;

        // Negated endpoint pairs, built once per predictor.
        const u64 ncx = pk2(-c0, -c2);
        const u64 ncy = pk2(-c1, -c3);

        // Pass 1: 16 independent distances (4 packed ops + 2 MUFU + 1 FADD).
        float d[LN];
        #pragma unroll
        for (int l = 0; l < LN; ++l) {
            u64 dx = add2(tx[l], ncx);
            u64 dy = add2(ty[l], ncy);
            u64 s  = fma2(dx, dx, mul2(dy, dy));
            float s1, s2;
            upk2(s1, s2, s);
            d[l] = asqrt(s1) + asqrt(s2);
        }

        // Pass 2: tree min (depth 4).
        float mm[8];
        #pragma unroll
        for (int i = 0; i < 8; ++i) mm[i] = fminf(d[2 * i], d[2 * i + 1]);
        #pragma unroll
        for (int i = 0; i < 4; ++i) mm[i] = fminf(mm[i], mm[i + 4]);
        mm[0] = fminf(mm[0], mm[2]);
        mm[1] = fminf(mm[1], mm[3]);
        const float m = fminf(mm[0], mm[1]);

        // Pass 3: tie mask (two independent OR chains).
        unsigned a0 = 0, a1 = 0;
        #pragma unroll
        for (int i = 0; i < 8; ++i) {
            a0 |= (d[i]     == m) ? (1u << i)       : 0u;
            a1 |= (d[i + 8] == m) ? (1u << (i + 8)) : 0u;
        }

        // thr = (m<2) ? m : -1; distances >= 0 so thr=-1 selects nothing.
        const float cnt = (m < 2.f) ? (float)__popc((a0 | a1) & tmask) : 0.f;

        // dist term: selected entries all equal m.
        loss = fmaf(m, cnt, loss);

        // Confidence term: sig = 1/(1+exp(-c4)).
        float sig = arcp(1.f + __expf(-c4));
        float e   = (cnt > 0.f) ? (sig - 1.f) : sig;
        loss = fmaf(e, e, loss);

        // Class term: cls_hard = 1 <=> c5 > 0.
        if (!(c5 > 0.f)) loss += cnt;
    }

    // ---- block reduction (deterministic) ----
    #pragma unroll
    for (int o = 16; o > 0; o >>= 1)
        loss += __shfl_xor_sync(0xffffffffu, loss, o);

    __shared__ float sw[TPB / 32];
    __shared__ bool  s_last;
    const int lane = tid & 31;
    const int wid  = tid >> 5;
    if (lane == 0) sw[wid] = loss;
    __syncthreads();
    if (wid == 0) {
        float v = (lane < TPB / 32) ? sw[lane] : 0.f;
        #pragma unroll
        for (int o = 2; o > 0; o >>= 1)
            v += __shfl_xor_sync(0xffffffffu, v, o);
        if (lane == 0) {
            g_partials[blockIdx.x] = v;
            __threadfence();
            unsigned t = atomicAdd(&g_ticket, 1u);
            s_last = (t == NBLK - 1);
        }
    }
    __syncthreads();

    // ---- last block folds all partials into the output ----
    if (s_last) {
        __threadfence();  // acquire: make all g_partials visible
        const int t = tid;
        float v = 0.f;
        for (int i = t; i < NBLK; i += TPB)   // fixed order: deterministic
            v += g_partials[i];
        __shared__ float s[TPB];
        s[t] = v;
        __syncthreads();
        #pragma unroll
        for (int o = TPB / 2; o > 0; o >>= 1) {
            if (t < o) s[t] += s[t + o];
            __syncthreads();
        }
        if (t == 0) {
            out[0] = s[0] * (1.0f / BSZ);
            g_ticket = 0;   // reset for the next (graph-replayed) launch
        }
    }
}

extern "C" void kernel_launch(void* const* d_in, const int* in_sizes, int n_in,
                              void* d_out, int out_size)
{
    const float* target = (const float*)d_in[0];
    const float* pred   = (const float*)d_in[1];
    float* out = (float*)d_out;

    yolino_main<<<NBLK, TPB>>>(target, pred, out);
}

// round 14
// speedup vs baseline: 1.1082x; 1.1082x over previous
#include <cuda_runtime.h>

#define GH 96
#define GW 96
#define HW (GH*GW)
#define BSZ 8
#define LN 16
#define PN 16
#define NCELL (BSZ*GH*GW)   /* 73728 */
#define TPB 128
#define NBLK (NCELL/TPB)    /* 576 */

__device__ float g_partials[NBLK];
__device__ unsigned int g_ticket;   // zero-init; last block resets it

typedef unsigned long long u64;

__device__ __forceinline__ float asqrt(float x) {
    float r;
    asm("sqrt.approx.f32 %0, %1;" : "=f"(r) : "f"(x));
    return r;
}
__device__ __forceinline__ float arcp(float x) {
    float r;
    asm("rcp.approx.f32 %0, %1;" : "=f"(r) : "f"(x));
    return r;
}
__device__ __forceinline__ u64 pk2(float a, float b) {
    u64 r; asm("mov.b64 %0, {%1, %2};" : "=l"(r) : "f"(a), "f"(b)); return r;
}
__device__ __forceinline__ void upk2(float& a, float& b, u64 v) {
    asm("mov.b64 {%0, %1}, %2;" : "=f"(a), "=f"(b) : "l"(v));
}
__device__ __forceinline__ u64 add2(u64 a, u64 b) {
    u64 r; asm("add.rn.f32x2 %0, %1, %2;" : "=l"(r) : "l"(a), "l"(b)); return r;
}
__device__ __forceinline__ u64 mul2(u64 a, u64 b) {
    u64 r; asm("mul.rn.f32x2 %0, %1, %2;" : "=l"(r) : "l"(a), "l"(b)); return r;
}
__device__ __forceinline__ u64 fma2(u64 a, u64 b, u64 c) {
    u64 r; asm("fma.rn.f32x2 %0, %1, %2, %3;" : "=l"(r) : "l"(a), "l"(b), "l"(c)); return r;
}

__global__ __launch_bounds__(TPB, 4)
void yolino_main(const float* __restrict__ target, const float* __restrict__ pred,
                 float* __restrict__ out)
{
    const int n = blockIdx.x * TPB + threadIdx.x;   // n in [0, NCELL)
    const int w  = n % GW;
    const int t1 = n / GW;
    const int h  = t1 % GH;
    const int b  = t1 / GH;

    const float* tb = target + b * (64 * HW) + h * GW + w;
    const float* pb = pred   + b * (96 * HW) + h * GW + w;

    // 16 target lines, packed per-line endpoint pairs: tx=(x1,x2), ty=(y1,y2).
    u64 tx[LN], ty[LN];
    unsigned tmask = 0;
    #pragma unroll
    for (int l = 0; l < LN; ++l) {
        float x1 = tb[(l * 4 + 0) * HW];
        float y1 = tb[(l * 4 + 1) * HW];
        float x2 = tb[(l * 4 + 2) * HW];
        float y2 = tb[(l * 4 + 3) * HW];
        tx[l] = pk2(x1, x2);
        ty[l] = pk2(y1, y2);
        float s = (x1 + y1) + (x2 + y2);
        if (s > 0.f) tmask |= (1u << l);
    }

    float loss = 0.f;

    // Prefetch predictor 0's six channels.
    float q0 = pb[0], q1 = pb[HW], q2 = pb[2 * HW],
          q3 = pb[3 * HW], q4 = pb[4 * HW], q5 = pb[5 * HW];

    #pragma unroll 1
    for (int p = 0; p < PN; ++p) {
        const float c0 = q0, c1 = q1, c2 = q2, c3 = q3, c4 = q4, c5 = q5;

        // Prefetch next predictor while we crunch this one.
        if (p + 1 < PN) {
            const float* nb = pb + (p + 1) * (6 * HW);
            q0 = nb[0];      q1 = nb[HW];     q2 = nb[2 * HW];
            q3 = nb[3 * HW]; q4 = nb[4 * HW]; q5 = nb[5 * HW];
        }

        // Negated endpoint pairs, built once per predictor.
        const u64 ncx = pk2(-c0, -c2);
        const u64 ncy = pk2(-c1, -c3);

        // Pass 1: per line compute e = d^2 = s1 + s2 + 2*sqrt(s1*s2)
        // (monotone in d = sqrt(s1)+sqrt(s2)): ONE sqrt per line, not two.
        float e[LN];
        #pragma unroll
        for (int l = 0; l < LN; ++l) {
            u64 dx = add2(tx[l], ncx);            // (x1-c0, x2-c2)
            u64 dy = add2(ty[l], ncy);            // (y1-c1, y2-c3)
            u64 s  = fma2(dx, dx, mul2(dy, dy));  // (s1, s2)
            float s1, s2;
            upk2(s1, s2, s);                       // register aliasing, free
            e[l] = fmaf(2.f, asqrt(s1 * s2), s1 + s2);
        }

        // Pass 2: tree min over e (depth 4) — same ordering as min over d.
        float mm[8];
        #pragma unroll
        for (int i = 0; i < 8; ++i) mm[i] = fminf(e[2 * i], e[2 * i + 1]);
        #pragma unroll
        for (int i = 0; i < 4; ++i) mm[i] = fminf(mm[i], mm[i + 4]);
        mm[0] = fminf(mm[0], mm[2]);
        mm[1] = fminf(mm[1], mm[3]);
        const float me = fminf(mm[0], mm[1]);

        // Pass 3: tie mask on e (ties in e <=> ties in d).
        unsigned a0 = 0, a1 = 0;
        #pragma unroll
        for (int i = 0; i < 8; ++i) {
            a0 |= (e[i]     == me) ? (1u << i)       : 0u;
            a1 |= (e[i + 8] == me) ? (1u << (i + 8)) : 0u;
        }

        // Recover the actual min distance with ONE sqrt per predictor.
        const float md = asqrt(me);

        // thr = (md<2) ? md : -1; distances >= 0 so thr=-1 selects nothing.
        const float cnt = (md < 2.f) ? (float)__popc((a0 | a1) & tmask) : 0.f;

        // dist term: selected entries all equal md.
        loss = fmaf(md, cnt, loss);

        // Confidence term: sig = 1/(1+exp(-c4)).
        float sig = arcp(1.f + __expf(-c4));
        float ee  = (cnt > 0.f) ? (sig - 1.f) : sig;
        loss = fmaf(ee, ee, loss);

        // Class term: cls_hard = 1 <=> c5 > 0.
        if (!(c5 > 0.f)) loss += cnt;
    }

    // ---- block reduction (deterministic) ----
    #pragma unroll
    for (int o = 16; o > 0; o >>= 1)
        loss += __shfl_xor_sync(0xffffffffu, loss, o);

    __shared__ float sw[TPB / 32];
    __shared__ bool  s_last;
    const int lane = threadIdx.x & 31;
    const int wid  = threadIdx.x >> 5;
    if (lane == 0) sw[wid] = loss;
    __syncthreads();
    if (wid == 0) {
        float v = (lane < TPB / 32) ? sw[lane] : 0.f;
        #pragma unroll
        for (int o = 2; o > 0; o >>= 1)
            v += __shfl_xor_sync(0xffffffffu, v, o);
        if (lane == 0) {
            g_partials[blockIdx.x] = v;
            __threadfence();
            unsigned t = atomicAdd(&g_ticket, 1u);
            s_last = (t == NBLK - 1);
        }
    }
    __syncthreads();

    // ---- last block folds all partials into the output ----
    if (s_last) {
        __threadfence();  // acquire: make all g_partials visible
        const int t = threadIdx.x;
        float v = 0.f;
        for (int i = t; i < NBLK; i += TPB)   // fixed order: deterministic
            v += g_partials[i];
        __shared__ float s[TPB];
        s[t] = v;
        __syncthreads();
        #pragma unroll
        for (int o = TPB / 2; o > 0; o >>= 1) {
            if (t < o) s[t] += s[t + o];
            __syncthreads();
        }
        if (t == 0) {
            out[0] = s[0] * (1.0f / BSZ);
            g_ticket = 0;   // reset for the next (graph-replayed) launch
        }
    }
}

extern "C" void kernel_launch(void* const* d_in, const int* in_sizes, int n_in,
                              void* d_out, int out_size)
{
    const float* target = (const float*)d_in[0];
    const float* pred   = (const float*)d_in[1];
    float* out = (float*)d_out;

    yolino_main<<<NBLK, TPB>>>(target, pred, out);
}